// round 3
// baseline (speedup 1.0000x reference)
#include <cuda_runtime.h>
#include <cuda_bf16.h>

#define NLAT 46
#define NLON 90
#define CH   256
#define SPX  (NLAT * NLON)   // 4140 spatial points

// Scratch: projected q/k/v in spatial-major layout [SPX][CH], plus segment offsets.
__device__ float g_q[SPX * CH];
__device__ float g_k[SPX * CH];
__device__ float g_v[SPX * CH];
__device__ int   g_off[NLAT + 1];

// ---------------------------------------------------------------------------
// Projection GEMM: out[s][n] = sum_c W[n][c] * X[c][s] + b[n]
//   X: [CH][SPX] (the natural b,c,h,w layout with b=1)
//   W: [CH][CH] row-major
//   out: [SPX][CH]  (spatial-major so attention gathers are coalesced)
// Tile: BM=64 (spatial) x BN=64 (out-ch) x BK=16, 256 threads, 4x4 micro-tile.
// ---------------------------------------------------------------------------
__global__ void proj_kernel(const float* __restrict__ X,
                            const float* __restrict__ W,
                            const float* __restrict__ bias,
                            int which)
{
    float* out = (which == 0) ? g_q : (which == 1) ? g_k : g_v;

    __shared__ __align__(16) float Xs[16][64];
    __shared__ __align__(16) float Ws[16][64];

    const int tid = threadIdx.x;
    const int s0  = blockIdx.x * 64;
    const int n0  = blockIdx.y * 64;

    const int tm = (tid >> 4) * 4;   // 0..60 (spatial within tile)
    const int tn = (tid & 15) * 4;   // 0..60 (out-ch within tile)

    float acc[4][4] = {};

    for (int c0 = 0; c0 < CH; c0 += 16) {
        // Load Xs[kk][sm] = X[(c0+kk)*SPX + s0+sm] : coalesced over sm
        #pragma unroll
        for (int r = 0; r < 4; ++r) {
            int idx = tid + 256 * r;
            int kk = idx >> 6, sm = idx & 63;
            int s = s0 + sm;
            Xs[kk][sm] = (s < SPX) ? X[(c0 + kk) * SPX + s] : 0.0f;
        }
        // Load Ws[kk][kn] = W[(n0+kn)*CH + c0+kk]
        #pragma unroll
        for (int r = 0; r < 4; ++r) {
            int idx = tid + 256 * r;
            int kn = idx >> 4, kk = idx & 15;
            Ws[kk][kn] = W[(n0 + kn) * CH + (c0 + kk)];
        }
        __syncthreads();

        #pragma unroll
        for (int kk = 0; kk < 16; ++kk) {
            float4 a = *(const float4*)&Xs[kk][tm];
            float4 w = *(const float4*)&Ws[kk][tn];
            float av[4] = {a.x, a.y, a.z, a.w};
            float wv[4] = {w.x, w.y, w.z, w.w};
            #pragma unroll
            for (int i = 0; i < 4; ++i)
                #pragma unroll
                for (int j = 0; j < 4; ++j)
                    acc[i][j] += av[i] * wv[j];
        }
        __syncthreads();
    }

    float bv[4];
    #pragma unroll
    for (int j = 0; j < 4; ++j) bv[j] = __ldg(&bias[n0 + tn + j]);

    #pragma unroll
    for (int i = 0; i < 4; ++i) {
        int s = s0 + tm + i;
        if (s < SPX) {
            float4 o;
            o.x = acc[i][0] + bv[0];
            o.y = acc[i][1] + bv[1];
            o.z = acc[i][2] + bv[2];
            o.w = acc[i][3] + bv[3];
            *(float4*)&out[s * CH + n0 + tn] = o;
        }
    }
}

// ---------------------------------------------------------------------------
// Segment offsets: g_off[t] = lower_bound(row_ids, t)  (row_ids sorted)
// ---------------------------------------------------------------------------
__global__ void offsets_kernel(const int* __restrict__ row_ids, int nnz)
{
    int t = threadIdx.x;
    if (t <= NLAT) {
        int lo = 0, hi = nnz;
        while (lo < hi) {
            int mid = (lo + hi) >> 1;
            if (row_ids[mid] < t) lo = mid + 1; else hi = mid;
        }
        g_off[t] = lo;
    }
}

// ---------------------------------------------------------------------------
// Neighborhood attention with online (flash-style) softmax.
// One warp per (t, wo) output point. Each lane owns 8 channels (2 x float4).
// out layout: [b=1][c][t][wo]  ->  out[c*SPX + t*NLON + wo]
// ---------------------------------------------------------------------------
__global__ void attn_kernel(const float* __restrict__ quad,
                            const int*   __restrict__ col_idx,
                            float*       __restrict__ out)
{
    int gw = (int)((blockIdx.x * blockDim.x + threadIdx.x) >> 5);
    if (gw >= SPX) return;                 // warp-uniform exit
    const int t    = gw / NLON;
    const int wo   = gw - t * NLON;
    const int lane = threadIdx.x & 31;

    const float4* qv = (const float4*)(g_q + gw * CH);
    const float4 q0 = qv[lane];
    const float4 q1 = qv[lane + 32];

    float m = -3.4e38f;
    float d = 0.0f;
    float4 a0 = make_float4(0.f, 0.f, 0.f, 0.f);
    float4 a1 = make_float4(0.f, 0.f, 0.f, 0.f);

    const int beg = g_off[t];
    const int end = g_off[t + 1];

    for (int n = beg; n < end; ++n) {
        int ci  = __ldg(&col_idx[n]);
        int hi  = ci / NLON;
        int wi  = ci - hi * NLON + wo;
        if (wi >= NLON) wi -= NLON;
        int base = (hi * NLON + wi) * CH;

        const float4* kv = (const float4*)(g_k + base);
        float4 k0 = kv[lane];
        float4 k1 = kv[lane + 32];

        float p = q0.x * k0.x + q0.y * k0.y + q0.z * k0.z + q0.w * k0.w
                + q1.x * k1.x + q1.y * k1.y + q1.z * k1.z + q1.w * k1.w;
        #pragma unroll
        for (int o = 16; o; o >>= 1)
            p += __shfl_xor_sync(0xffffffffu, p, o);

        float w  = __ldg(&quad[hi]);
        float mn = fmaxf(m, p);
        float sc = __expf(m - mn);        // first iter: exp(-huge) -> 0
        float e  = __expf(p - mn) * w;

        const float4* vv = (const float4*)(g_v + base);
        float4 v0 = vv[lane];
        float4 v1 = vv[lane + 32];

        d = d * sc + e;
        a0.x = a0.x * sc + e * v0.x;
        a0.y = a0.y * sc + e * v0.y;
        a0.z = a0.z * sc + e * v0.z;
        a0.w = a0.w * sc + e * v0.w;
        a1.x = a1.x * sc + e * v1.x;
        a1.y = a1.y * sc + e * v1.y;
        a1.z = a1.z * sc + e * v1.z;
        a1.w = a1.w * sc + e * v1.w;
        m = mn;
    }

    const float inv = 1.0f / d;
    const int pos = gw;                   // t*NLON + wo
    const int c0 = lane * 4;
    out[(c0 + 0) * SPX + pos] = a0.x * inv;
    out[(c0 + 1) * SPX + pos] = a0.y * inv;
    out[(c0 + 2) * SPX + pos] = a0.z * inv;
    out[(c0 + 3) * SPX + pos] = a0.w * inv;
    out[(c0 + 128) * SPX + pos] = a1.x * inv;
    out[(c0 + 129) * SPX + pos] = a1.y * inv;
    out[(c0 + 130) * SPX + pos] = a1.z * inv;
    out[(c0 + 131) * SPX + pos] = a1.w * inv;
}

// ---------------------------------------------------------------------------
extern "C" void kernel_launch(void* const* d_in, const int* in_sizes, int n_in,
                              void* d_out, int out_size)
{
    const float* qo   = (const float*)d_in[0];
    const float* ki   = (const float*)d_in[1];
    const float* vi   = (const float*)d_in[2];
    const float* q_w  = (const float*)d_in[3];
    const float* k_w  = (const float*)d_in[4];
    const float* v_w  = (const float*)d_in[5];
    const float* q_b  = (const float*)d_in[6];
    const float* k_b  = (const float*)d_in[7];
    const float* v_b  = (const float*)d_in[8];
    const float* quad = (const float*)d_in[9];
    const int* row_ids = (const int*)d_in[10];
    const int* col_idx = (const int*)d_in[11];
    const int nnz = in_sizes[10];

    float* out = (float*)d_out;

    dim3 gg((SPX + 63) / 64, CH / 64);
    proj_kernel<<<gg, 256>>>(qo, q_w, q_b, 0);
    proj_kernel<<<gg, 256>>>(ki, k_w, k_b, 1);
    proj_kernel<<<gg, 256>>>(vi, v_w, v_b, 2);

    offsets_kernel<<<1, 64>>>(row_ids, nnz);

    int total_threads = SPX * 32;
    attn_kernel<<<(total_threads + 255) / 256, 256>>>(quad, col_idx, out);
}

// round 4
// speedup vs baseline: 1.5422x; 1.5422x over previous
#include <cuda_runtime.h>
#include <cuda_bf16.h>

#define NLAT 46
#define NLON 90
#define CH   256
#define SPX  (NLAT * NLON)   // 4140 spatial points

// Scratch: projected q/k/v in spatial-major layout [SPX][CH], plus segment offsets.
__device__ float g_q[SPX * CH];
__device__ float g_k[SPX * CH];
__device__ float g_v[SPX * CH];
__device__ int   g_off[NLAT + 1];

// ---------------------------------------------------------------------------
// Fused projection GEMM (q, k, v selected by blockIdx.z):
//   out[s][n] = sum_c W[n][c] * X[c][s] + b[n]
//   X: [CH][SPX], W: [CH][CH] row-major, out: [SPX][CH] (spatial-major).
// Tile: BM=64 x BN=64 x BK=16, 64 threads, 8x8 micro-tile split as
// rows {tm..tm+3, tm+32..tm+35} x cols {tn..tn+3, tn+32..tn+35}
// -> 1 B smem traffic per FMA (half the crossbar limit), conflict-free LDS.
// Block (0,0,0) additionally computes segment offsets from row_ids.
// ---------------------------------------------------------------------------
__global__ void __launch_bounds__(64) proj_kernel(
    const float* __restrict__ qo, const float* __restrict__ ki,
    const float* __restrict__ vi,
    const float* __restrict__ q_w, const float* __restrict__ k_w,
    const float* __restrict__ v_w,
    const float* __restrict__ q_b, const float* __restrict__ k_b,
    const float* __restrict__ v_b,
    const int* __restrict__ row_ids, int nnz)
{
    const int which = blockIdx.z;
    const float* X    = (which == 0) ? qo  : (which == 1) ? ki  : vi;
    const float* W    = (which == 0) ? q_w : (which == 1) ? k_w : v_w;
    const float* bias = (which == 0) ? q_b : (which == 1) ? k_b : v_b;
    float* out        = (which == 0) ? g_q : (which == 1) ? g_k : g_v;

    const int tid = threadIdx.x;

    // Fold in segment-offset computation (independent of GEMM work).
    if (which == 0 && blockIdx.x == 0 && blockIdx.y == 0 && tid <= NLAT) {
        int lo = 0, hi = nnz;
        while (lo < hi) {
            int mid = (lo + hi) >> 1;
            if (row_ids[mid] < tid) lo = mid + 1; else hi = mid;
        }
        g_off[tid] = lo;
    }

    __shared__ __align__(16) float Xs[16][64];
    __shared__ __align__(16) float Ws[16][68];   // pad to break STS conflicts

    const int s0 = blockIdx.x * 64;
    const int n0 = blockIdx.y * 64;

    const int tm = (tid >> 3) * 4;   // 0..28
    const int tn = (tid & 7) * 4;    // 0..28

    float acc[8][8] = {};

    for (int c0 = 0; c0 < CH; c0 += 16) {
        // Xs[kk][sm] = X[(c0+kk)*SPX + s0+sm], vectorized (SPX % 4 == 0)
        #pragma unroll
        for (int r = 0; r < 4; ++r) {
            int idx = r * 64 + tid;
            int kk = idx >> 4, sm4 = idx & 15;
            int s = s0 + sm4 * 4;
            float4 xv = make_float4(0.f, 0.f, 0.f, 0.f);
            if (s < SPX)
                xv = *(const float4*)&X[(c0 + kk) * SPX + s];
            *(float4*)&Xs[kk][sm4 * 4] = xv;
        }
        // Ws[kk][kn] = W[(n0+kn)*CH + c0+kk] (transpose via 4x STS.32)
        #pragma unroll
        for (int r = 0; r < 4; ++r) {
            int idx = r * 64 + tid;
            int kn = idx >> 2, kk4 = (idx & 3) * 4;
            float4 wv = *(const float4*)&W[(n0 + kn) * CH + c0 + kk4];
            Ws[kk4 + 0][kn] = wv.x;
            Ws[kk4 + 1][kn] = wv.y;
            Ws[kk4 + 2][kn] = wv.z;
            Ws[kk4 + 3][kn] = wv.w;
        }
        __syncthreads();

        #pragma unroll
        for (int kk = 0; kk < 16; ++kk) {
            float4 a0 = *(const float4*)&Xs[kk][tm];
            float4 a1 = *(const float4*)&Xs[kk][tm + 32];
            float4 w0 = *(const float4*)&Ws[kk][tn];
            float4 w1 = *(const float4*)&Ws[kk][tn + 32];
            float av[8] = {a0.x, a0.y, a0.z, a0.w, a1.x, a1.y, a1.z, a1.w};
            float wv[8] = {w0.x, w0.y, w0.z, w0.w, w1.x, w1.y, w1.z, w1.w};
            #pragma unroll
            for (int i = 0; i < 8; ++i)
                #pragma unroll
                for (int j = 0; j < 8; ++j)
                    acc[i][j] += av[i] * wv[j];
        }
        __syncthreads();
    }

    float bv[8];
    #pragma unroll
    for (int j = 0; j < 4; ++j) {
        bv[j]     = __ldg(&bias[n0 + tn + j]);
        bv[j + 4] = __ldg(&bias[n0 + tn + 32 + j]);
    }

    #pragma unroll
    for (int i = 0; i < 8; ++i) {
        int s = s0 + ((i < 4) ? (tm + i) : (tm + 32 + i - 4));
        if (s < SPX) {
            float4 o0, o1;
            o0.x = acc[i][0] + bv[0];  o0.y = acc[i][1] + bv[1];
            o0.z = acc[i][2] + bv[2];  o0.w = acc[i][3] + bv[3];
            o1.x = acc[i][4] + bv[4];  o1.y = acc[i][5] + bv[5];
            o1.z = acc[i][6] + bv[6];  o1.w = acc[i][7] + bv[7];
            *(float4*)&out[s * CH + n0 + tn]      = o0;
            *(float4*)&out[s * CH + n0 + tn + 32] = o1;
        }
    }
}

// ---------------------------------------------------------------------------
// Neighborhood attention, softmax WITHOUT running max (|q.k| is small, so
// exp() is safe in fp32 and iterations become independent -> pipelined).
// One warp per (t, wo); lane owns 8 channels (2 x float4). 8 warps/block.
// Output staged through padded smem for 32B-coalesced stores.
// out layout: [c][t][wo] -> out[c*SPX + pos]
// ---------------------------------------------------------------------------
__global__ void __launch_bounds__(256) attn_kernel(
    const float* __restrict__ quad,
    const int*   __restrict__ col_idx,
    float*       __restrict__ out)
{
    __shared__ float sbuf[CH][9];     // [channel][pos-in-block], padded

    const int warp = threadIdx.x >> 5;
    const int lane = threadIdx.x & 31;
    const int pos0 = blockIdx.x * 8;
    const int gw   = pos0 + warp;

    if (gw < SPX) {
        const int t  = gw / NLON;
        const int wo = gw - t * NLON;

        const float4* qv = (const float4*)(g_q + gw * CH);
        const float4 q0 = qv[lane];
        const float4 q1 = qv[lane + 32];

        float d = 0.0f;
        float4 a0 = make_float4(0.f, 0.f, 0.f, 0.f);
        float4 a1 = make_float4(0.f, 0.f, 0.f, 0.f);

        const int beg = g_off[t];
        const int end = g_off[t + 1];

        #pragma unroll 2
        for (int n = beg; n < end; ++n) {
            int ci = __ldg(&col_idx[n]);
            int hi = ci / NLON;
            int wi = ci - hi * NLON + wo;
            if (wi >= NLON) wi -= NLON;
            int base = (hi * NLON + wi) * CH;

            const float4* kv = (const float4*)(g_k + base);
            float4 k0 = kv[lane];
            float4 k1 = kv[lane + 32];
            const float4* vv = (const float4*)(g_v + base);
            float4 v0 = vv[lane];
            float4 v1 = vv[lane + 32];

            float p = q0.x * k0.x + q0.y * k0.y + q0.z * k0.z + q0.w * k0.w
                    + q1.x * k1.x + q1.y * k1.y + q1.z * k1.z + q1.w * k1.w;
            #pragma unroll
            for (int o = 16; o; o >>= 1)
                p += __shfl_xor_sync(0xffffffffu, p, o);

            float e = __expf(p) * __ldg(&quad[hi]);

            d += e;
            a0.x += e * v0.x;  a0.y += e * v0.y;
            a0.z += e * v0.z;  a0.w += e * v0.w;
            a1.x += e * v1.x;  a1.y += e * v1.y;
            a1.z += e * v1.z;  a1.w += e * v1.w;
        }

        const float inv = 1.0f / d;
        const int c0 = lane * 4;
        sbuf[c0 + 0][warp] = a0.x * inv;
        sbuf[c0 + 1][warp] = a0.y * inv;
        sbuf[c0 + 2][warp] = a0.z * inv;
        sbuf[c0 + 3][warp] = a0.w * inv;
        sbuf[c0 + 128][warp] = a1.x * inv;
        sbuf[c0 + 129][warp] = a1.y * inv;
        sbuf[c0 + 130][warp] = a1.z * inv;
        sbuf[c0 + 131][warp] = a1.w * inv;
    }
    __syncthreads();

    // Coalesced write-out: 8 consecutive positions per channel row.
    const int p = threadIdx.x & 7;
    const int cb = threadIdx.x >> 3;      // 0..31
    if (pos0 + p < SPX) {
        #pragma unroll
        for (int j = 0; j < 8; ++j) {
            int c = cb + j * 32;
            out[c * SPX + pos0 + p] = sbuf[c][p];
        }
    }
}

// ---------------------------------------------------------------------------
extern "C" void kernel_launch(void* const* d_in, const int* in_sizes, int n_in,
                              void* d_out, int out_size)
{
    const float* qo   = (const float*)d_in[0];
    const float* ki   = (const float*)d_in[1];
    const float* vi   = (const float*)d_in[2];
    const float* q_w  = (const float*)d_in[3];
    const float* k_w  = (const float*)d_in[4];
    const float* v_w  = (const float*)d_in[5];
    const float* q_b  = (const float*)d_in[6];
    const float* k_b  = (const float*)d_in[7];
    const float* v_b  = (const float*)d_in[8];
    const float* quad = (const float*)d_in[9];
    const int* row_ids = (const int*)d_in[10];
    const int* col_idx = (const int*)d_in[11];
    const int nnz = in_sizes[10];

    float* out = (float*)d_out;

    dim3 gg((SPX + 63) / 64, CH / 64, 3);
    proj_kernel<<<gg, 64>>>(qo, ki, vi, q_w, k_w, v_w, q_b, k_b, v_b,
                            row_ids, nnz);

    attn_kernel<<<(SPX + 7) / 8, 256>>>(quad, col_idx, out);
}

// round 6
// speedup vs baseline: 2.1074x; 1.3665x over previous
#include <cuda_runtime.h>
#include <cuda_bf16.h>

#define NLAT 46
#define NLON 90
#define CH   256
#define SPX  (NLAT * NLON)   // 4140 spatial points

#define HEAVY_BLOCKS (2 * NLON)                    // rows 0 and 45, one CTA per wo
#define LIGHT_POS    ((NLAT - 2) * NLON)           // 3960 positions, rows 1..44
#define LIGHT_BLOCKS (LIGHT_POS / 8)               // 495

// Scratch: projected q/k/v in spatial-major layout [SPX][CH], plus segment offsets.
__device__ float g_q[SPX * CH];
__device__ float g_k[SPX * CH];
__device__ float g_v[SPX * CH];
__device__ int   g_off[NLAT + 1];

// ---------------------------------------------------------------------------
// Fused projection GEMM (q, k, v selected by blockIdx.z):
//   out[s][n] = sum_c W[n][c] * X[c][s] + b[n]
// Tile: BM=64 x BN=64 x BK=16, 64 threads, 8x8 micro-tile.
// Block (0,0,0) additionally computes segment offsets from row_ids.
// ---------------------------------------------------------------------------
__global__ void __launch_bounds__(64) proj_kernel(
    const float* __restrict__ qo, const float* __restrict__ ki,
    const float* __restrict__ vi,
    const float* __restrict__ q_w, const float* __restrict__ k_w,
    const float* __restrict__ v_w,
    const float* __restrict__ q_b, const float* __restrict__ k_b,
    const float* __restrict__ v_b,
    const int* __restrict__ row_ids, int nnz)
{
    const int which = blockIdx.z;
    const float* X    = (which == 0) ? qo  : (which == 1) ? ki  : vi;
    const float* W    = (which == 0) ? q_w : (which == 1) ? k_w : v_w;
    const float* bias = (which == 0) ? q_b : (which == 1) ? k_b : v_b;
    float* out        = (which == 0) ? g_q : (which == 1) ? g_k : g_v;

    const int tid = threadIdx.x;

    if (which == 0 && blockIdx.x == 0 && blockIdx.y == 0 && tid <= NLAT) {
        int lo = 0, hi = nnz;
        while (lo < hi) {
            int mid = (lo + hi) >> 1;
            if (row_ids[mid] < tid) lo = mid + 1; else hi = mid;
        }
        g_off[tid] = lo;
    }

    __shared__ __align__(16) float Xs[16][64];
    __shared__ __align__(16) float Ws[16][68];

    const int s0 = blockIdx.x * 64;
    const int n0 = blockIdx.y * 64;

    const int tm = (tid >> 3) * 4;
    const int tn = (tid & 7) * 4;

    float acc[8][8] = {};

    for (int c0 = 0; c0 < CH; c0 += 16) {
        #pragma unroll
        for (int r = 0; r < 4; ++r) {
            int idx = r * 64 + tid;
            int kk = idx >> 4, sm4 = idx & 15;
            int s = s0 + sm4 * 4;
            float4 xv = make_float4(0.f, 0.f, 0.f, 0.f);
            if (s < SPX)
                xv = *(const float4*)&X[(c0 + kk) * SPX + s];
            *(float4*)&Xs[kk][sm4 * 4] = xv;
        }
        #pragma unroll
        for (int r = 0; r < 4; ++r) {
            int idx = r * 64 + tid;
            int kn = idx >> 2, kk4 = (idx & 3) * 4;
            float4 wv = *(const float4*)&W[(n0 + kn) * CH + c0 + kk4];
            Ws[kk4 + 0][kn] = wv.x;
            Ws[kk4 + 1][kn] = wv.y;
            Ws[kk4 + 2][kn] = wv.z;
            Ws[kk4 + 3][kn] = wv.w;
        }
        __syncthreads();

        #pragma unroll
        for (int kk = 0; kk < 16; ++kk) {
            float4 a0 = *(const float4*)&Xs[kk][tm];
            float4 a1 = *(const float4*)&Xs[kk][tm + 32];
            float4 w0 = *(const float4*)&Ws[kk][tn];
            float4 w1 = *(const float4*)&Ws[kk][tn + 32];
            float av[8] = {a0.x, a0.y, a0.z, a0.w, a1.x, a1.y, a1.z, a1.w};
            float wv[8] = {w0.x, w0.y, w0.z, w0.w, w1.x, w1.y, w1.z, w1.w};
            #pragma unroll
            for (int i = 0; i < 8; ++i)
                #pragma unroll
                for (int j = 0; j < 8; ++j)
                    acc[i][j] += av[i] * wv[j];
        }
        __syncthreads();
    }

    float bv[8];
    #pragma unroll
    for (int j = 0; j < 4; ++j) {
        bv[j]     = __ldg(&bias[n0 + tn + j]);
        bv[j + 4] = __ldg(&bias[n0 + tn + 32 + j]);
    }

    #pragma unroll
    for (int i = 0; i < 8; ++i) {
        int s = s0 + ((i < 4) ? (tm + i) : (tm + 32 + i - 4));
        if (s < SPX) {
            float4 o0, o1;
            o0.x = acc[i][0] + bv[0];  o0.y = acc[i][1] + bv[1];
            o0.z = acc[i][2] + bv[2];  o0.w = acc[i][3] + bv[3];
            o1.x = acc[i][4] + bv[4];  o1.y = acc[i][5] + bv[5];
            o1.z = acc[i][6] + bv[6];  o1.w = acc[i][7] + bv[7];
            *(float4*)&out[s * CH + n0 + tn]      = o0;
            *(float4*)&out[s * CH + n0 + tn + 32] = o1;
        }
    }
}

// ---------------------------------------------------------------------------
// Attention body for one neighbor: returns nothing, accumulates into d/a0/a1.
// ---------------------------------------------------------------------------
__device__ __forceinline__ void attn_step(
    int ci, int wo, int lane,
    const float4 q0, const float4 q1,
    const float* __restrict__ quad,
    float& d, float4& a0, float4& a1)
{
    int hi = ci / NLON;
    int wi = ci - hi * NLON + wo;
    if (wi >= NLON) wi -= NLON;
    int base = (hi * NLON + wi) * CH;

    const float4* kv = (const float4*)(g_k + base);
    float4 k0 = kv[lane];
    float4 k1 = kv[lane + 32];
    const float4* vv = (const float4*)(g_v + base);
    float4 v0 = vv[lane];
    float4 v1 = vv[lane + 32];

    float p = q0.x * k0.x + q0.y * k0.y + q0.z * k0.z + q0.w * k0.w
            + q1.x * k1.x + q1.y * k1.y + q1.z * k1.z + q1.w * k1.w;
    #pragma unroll
    for (int o = 16; o; o >>= 1)
        p += __shfl_xor_sync(0xffffffffu, p, o);

    float e = __expf(p) * __ldg(&quad[hi]);

    d += e;
    a0.x += e * v0.x;  a0.y += e * v0.y;
    a0.z += e * v0.z;  a0.w += e * v0.w;
    a1.x += e * v1.x;  a1.y += e * v1.y;
    a1.z += e * v1.z;  a1.w += e * v1.w;
}

// ---------------------------------------------------------------------------
// Attention. Two CTA roles:
//   blockIdx.x < 180  : HEAVY — one CTA per pole output point (rows 0, 45).
//                       8 warps stride the ~180 neighbors, smem-combine.
//   else              : LIGHT — 8 warps x 1 output point each (rows 1..44),
//                       smem-transposed coalesced store.
// Valid because the no-max softmax accumulators are pure sums.
// out layout: [c][t][wo] -> out[c*SPX + pos]
// ---------------------------------------------------------------------------
__global__ void __launch_bounds__(256) attn_kernel(
    const float* __restrict__ quad,
    const int*   __restrict__ col_idx,
    float*       __restrict__ out)
{
    __shared__ float smem[2312];   // heavy: [8][256]+[8]  | light: [256][9]

    const int warp = threadIdx.x >> 5;
    const int lane = threadIdx.x & 31;

    if (blockIdx.x < HEAVY_BLOCKS) {
        // ---------------- HEAVY: one output point, 8 warps split neighbors
        const int bi  = blockIdx.x;
        const int t   = (bi < NLON) ? 0 : (NLAT - 1);
        const int wo  = (bi < NLON) ? bi : bi - NLON;
        const int pos = t * NLON + wo;

        const float4* qv = (const float4*)(g_q + pos * CH);
        const float4 q0 = qv[lane];
        const float4 q1 = qv[lane + 32];

        float d = 0.0f;
        float4 a0 = make_float4(0.f, 0.f, 0.f, 0.f);
        float4 a1 = make_float4(0.f, 0.f, 0.f, 0.f);

        const int beg = g_off[t];
        const int end = g_off[t + 1];

        #pragma unroll 2
        for (int n = beg + warp; n < end; n += 8) {
            int ci = __ldg(&col_idx[n]);
            attn_step(ci, wo, lane, q0, q1, quad, d, a0, a1);
        }

        // Per-warp partials -> smem
        float* sb = smem + warp * 256;
        *(float4*)&sb[lane * 4]       = a0;
        *(float4*)&sb[128 + lane * 4] = a1;
        if (lane == 0) smem[2048 + warp] = d;
        __syncthreads();

        // 256 threads: thread c sums channel c over 8 warps.
        const int c = threadIdx.x;
        float s = 0.0f, dt = 0.0f;
        #pragma unroll
        for (int w = 0; w < 8; ++w) s  += smem[w * 256 + c];
        #pragma unroll
        for (int w = 0; w < 8; ++w) dt += smem[2048 + w];
        out[c * SPX + pos] = s / dt;
    } else {
        // ---------------- LIGHT: 8 output points (rows 1..44)
        const int pos0 = NLON + (blockIdx.x - HEAVY_BLOCKS) * 8;
        const int gw   = pos0 + warp;

        const int t  = gw / NLON;
        const int wo = gw - t * NLON;

        const float4* qv = (const float4*)(g_q + gw * CH);
        const float4 q0 = qv[lane];
        const float4 q1 = qv[lane + 32];

        float d = 0.0f;
        float4 a0 = make_float4(0.f, 0.f, 0.f, 0.f);
        float4 a1 = make_float4(0.f, 0.f, 0.f, 0.f);

        const int beg = g_off[t];
        const int end = g_off[t + 1];

        #pragma unroll 2
        for (int n = beg; n < end; ++n) {
            int ci = __ldg(&col_idx[n]);
            attn_step(ci, wo, lane, q0, q1, quad, d, a0, a1);
        }

        const float inv = 1.0f / d;
        const int c0 = lane * 4;
        smem[(c0 + 0) * 9 + warp] = a0.x * inv;
        smem[(c0 + 1) * 9 + warp] = a0.y * inv;
        smem[(c0 + 2) * 9 + warp] = a0.z * inv;
        smem[(c0 + 3) * 9 + warp] = a0.w * inv;
        smem[(c0 + 128) * 9 + warp] = a1.x * inv;
        smem[(c0 + 129) * 9 + warp] = a1.y * inv;
        smem[(c0 + 130) * 9 + warp] = a1.z * inv;
        smem[(c0 + 131) * 9 + warp] = a1.w * inv;
        __syncthreads();

        // Coalesced write-out: 8 consecutive positions per channel row.
        const int p  = threadIdx.x & 7;
        const int cb = threadIdx.x >> 3;
        #pragma unroll
        for (int j = 0; j < 8; ++j) {
            int c = cb + j * 32;
            out[c * SPX + pos0 + p] = smem[c * 9 + p];
        }
    }
}

// ---------------------------------------------------------------------------
extern "C" void kernel_launch(void* const* d_in, const int* in_sizes, int n_in,
                              void* d_out, int out_size)
{
    const float* qo   = (const float*)d_in[0];
    const float* ki   = (const float*)d_in[1];
    const float* vi   = (const float*)d_in[2];
    const float* q_w  = (const float*)d_in[3];
    const float* k_w  = (const float*)d_in[4];
    const float* v_w  = (const float*)d_in[5];
    const float* q_b  = (const float*)d_in[6];
    const float* k_b  = (const float*)d_in[7];
    const float* v_b  = (const float*)d_in[8];
    const float* quad = (const float*)d_in[9];
    const int* row_ids = (const int*)d_in[10];
    const int* col_idx = (const int*)d_in[11];
    const int nnz = in_sizes[10];

    float* out = (float*)d_out;

    dim3 gg((SPX + 63) / 64, CH / 64, 3);
    proj_kernel<<<gg, 64>>>(qo, ki, vi, q_w, k_w, v_w, q_b, k_b, v_b,
                            row_ids, nnz);

    attn_kernel<<<HEAVY_BLOCKS + LIGHT_BLOCKS, 256>>>(quad, col_idx, out);
}